// round 12
// baseline (speedup 1.0000x reference)
#include <cuda_runtime.h>
#include <cstdint>

// SeparableConv3D: x[8,3,32,256,256] fp32, depthwise K=5 cross-correlation
// along W, then H, then T, zero 'same' padding each stage.
//
// Fused, 2-rows-per-iteration software pipeline (LDG prefetch):
//   phase A: prefetch 2 x-rows into registers (item A: all threads,
//            item B: threads 128-191), commit via aligned STS.128
//   phase B (lane=t, wg=w-quad): W-conv via 4 aligned LDS.64 + H-conv ring,
//            store s into PAIR-INTERLEAVED staging sbufP[p=w/2][t][2]
//   phase C (threads 0-127; thread = (pair p, t-seg, row)): T-conv over
//            8t x 2w = 16 outputs from 6 LDS.128 (1.5x read amp), rolling
//            3-quad consume to cap live registers; 8x STG.64 coalesced
//   ONE __syncthreads per 2 h-rows.

#define NN 8
#define CC 3
#define TT 32
#define HH 256
#define WW 256
#define KK 5

#define WT 32                 // w outputs per block
#define HC 32                 // h rows per block -> grid = 24*8*8 = 1536
#define NIT ((HC + 4) / 2)    // 18 iterations of 2 rows
#define XSTRIDE 44            // x slab row stride (conflict-free)
#define PSTR 68               // sbufP per-pair stride (floats): 2*TT + 4 pad

__global__ void __launch_bounds__(256, 4)
sepconv3d_fused(const float* __restrict__ x,
                const float* __restrict__ w1,   // along W
                const float* __restrict__ w2,   // along H
                const float* __restrict__ w3,   // along T
                float* __restrict__ out)
{
    __shared__ float xbuf[2][2][TT * XSTRIDE];       // [buf][row]
    __shared__ float sbufP[2][2][(WT / 2) * PSTR];   // [buf][row][pair][t][2]

    const int tid  = threadIdx.x;
    const int lane = tid & 31;     // phase B: = t
    const int wg   = tid >> 5;     // phase B: w-quad

    const int bid = blockIdx.x;               // 0..1535
    const int nc  = bid >> 6;                  // n*3+c
    const int rem = bid & 63;
    const int wt  = rem >> 3;                   // 0..7
    const int hcb = rem & 7;                    // 0..7
    const int c   = nc % CC;

    const int w0 = wt * WT;
    const int h0 = hcb * HC;
    const size_t HW = (size_t)HH * WW;

    const float wW0 = w1[c*KK+0], wW1 = w1[c*KK+1], wW2 = w1[c*KK+2], wW3 = w1[c*KK+3], wW4 = w1[c*KK+4];
    const float wH0 = w2[c*KK+0], wH1 = w2[c*KK+1], wH2 = w2[c*KK+2], wH3 = w2[c*KK+3], wH4 = w2[c*KK+4];
    const float wT0 = w3[c*KK+0], wT1 = w3[c*KK+1], wT2 = w3[c*KK+2], wT3 = w3[c*KK+3], wT4 = w3[c*KK+4];

    const float* xb = x   + (size_t)nc * (TT * HW);
    float*       ob = out + (size_t)nc * (TT * HW);

    // ---- slab-load geometry: item A = tid (all), item B = threads 128-191 ----
    const int trA = tid / 10,  qA = tid - trA * 10;
    const bool hasB = (tid >= 128) && (tid < 192);
    const int iB  = 256 + (tid - 128);
    const int trB = iB / 10,   qB = iB - trB * 10;
    const int gwA = w0 - 4 + 4 * qA;
    const int gwB = w0 - 4 + 4 * qB;
    const bool wvA = (gwA >= 0) && (gwA < WW);
    const bool wvB = hasB && (gwB >= 0) && (gwB < WW);
    const float* gA = xb + (size_t)trA * HW + (wvA ? gwA : 0);   // + h*WW
    const float* gB = xb + (size_t)trB * HW + (wvB ? gwB : 0);

    // smem commit addresses (aligned STS.128)
    float* const xsA00 = &xbuf[0][0][trA * XSTRIDE + 4 * qA];
    float* const xsA01 = &xbuf[0][1][trA * XSTRIDE + 4 * qA];
    float* const xsA10 = &xbuf[1][0][trA * XSTRIDE + 4 * qA];
    float* const xsA11 = &xbuf[1][1][trA * XSTRIDE + 4 * qA];
    float* const xsB00 = &xbuf[0][0][trB * XSTRIDE + 4 * qB];
    float* const xsB01 = &xbuf[0][1][trB * XSTRIDE + 4 * qB];
    float* const xsB10 = &xbuf[1][0][trB * XSTRIDE + 4 * qB];
    float* const xsB11 = &xbuf[1][1][trB * XSTRIDE + 4 * qB];

    // ---- phase C geometry (threads 0-127): p = pair, seg = 8t segment, rr = row ----
    const bool doC = (tid < 128);
    const int p    = tid & 15;           // w pair: w = w0 + 2p, 2p+1
    const int rest = (tid >> 4) & 7;     // 0..7
    const int seg  = rest & 3;           // t segment (8 t each)
    const int rr   = rest >> 2;          // row 0/1
    const int t0   = 8 * seg;
    const int pbase = p * PSTR;
    // quad offsets Qk covers t = t0-2+2k, t0-1+2k (x2 w interleaved)
    const int qoff0 = pbase + max(2 * t0 - 4, 0);     // clamped; masked if seg==0
    const int qoff1 = pbase + 2 * t0;
    const int qoff2 = pbase + 2 * t0 + 4;
    const int qoff3 = pbase + 2 * t0 + 8;
    const int qoff4 = pbase + 2 * t0 + 12;
    const int qoff5 = pbase + min(2 * t0 + 16, 2 * TT - 8);  // clamped; masked if seg==3
    const float mlo = (seg == 0) ? 0.f : 1.f;
    const float mhi = (seg == 3) ? 0.f : 1.f;
    // op advances 2 rows per iter; at iter ii it points at row h0 + 2ii - 6 + rr
    float* op = ob + (size_t)t0 * HW + w0 + 2 * p
                   + (size_t)(h0 + rr) * WW - 6 * WW;

    // H-conv register ring: g1..g4 = W-conv of the last 4 input rows
    float4 g1 = {0,0,0,0}, g2 = {0,0,0,0}, g3 = {0,0,0,0}, g4 = {0,0,0,0};
    const int scolbase = 4 * wg;
    float* const sbP00 = &sbufP[0][0][(2 * wg) * PSTR + 2 * lane];
    float* const sbP01 = &sbufP[0][1][(2 * wg) * PSTR + 2 * lane];
    float* const sbP10 = &sbufP[1][0][(2 * wg) * PSTR + 2 * lane];
    float* const sbP11 = &sbufP[1][1][(2 * wg) * PSTR + 2 * lane];

    // ---- prologue: rows h0-2, h0-1 into xbuf[0][0..1] ----
    {
        float4 v0 = {0,0,0,0}, v1 = {0,0,0,0}, u0 = {0,0,0,0}, u1 = {0,0,0,0};
        if (wvA && h0 - 2 >= 0) v0 = *reinterpret_cast<const float4*>(gA + (size_t)(h0 - 2) * WW);
        if (wvA && h0 - 1 >= 0) v1 = *reinterpret_cast<const float4*>(gA + (size_t)(h0 - 1) * WW);
        *reinterpret_cast<float4*>(xsA00) = v0;
        *reinterpret_cast<float4*>(xsA01) = v1;
        if (hasB) {
            if (wvB && h0 - 2 >= 0) u0 = *reinterpret_cast<const float4*>(gB + (size_t)(h0 - 2) * WW);
            if (wvB && h0 - 1 >= 0) u1 = *reinterpret_cast<const float4*>(gB + (size_t)(h0 - 1) * WW);
            *reinterpret_cast<float4*>(xsB00) = u0;
            *reinterpret_cast<float4*>(xsB01) = u1;
        }
    }
    __syncthreads();

    #pragma unroll 2
    for (int ii = 0; ii < NIT; ++ii) {
        const int cur = ii & 1;

        // ---- 1. prefetch rows h0+2ii, h0+2ii+1 (for next iteration) ----
        float4 pa0 = {0,0,0,0}, pa1 = {0,0,0,0}, pb0 = {0,0,0,0}, pb1 = {0,0,0,0};
        {
            const bool iv = (ii + 1 < NIT);
            const int ha = h0 + 2 * ii;
            const int hb = ha + 1;
            if (iv && wvA && ha < HH) pa0 = *reinterpret_cast<const float4*>(gA + (size_t)ha * WW);
            if (iv && wvA && hb < HH) pa1 = *reinterpret_cast<const float4*>(gA + (size_t)hb * WW);
            if (iv && wvB && ha < HH) pb0 = *reinterpret_cast<const float4*>(gB + (size_t)ha * WW);
            if (iv && wvB && hb < HH) pb1 = *reinterpret_cast<const float4*>(gB + (size_t)hb * WW);
        }

        // ---- 2. phase B: W-conv both rows (4x LDS.64 each), H-conv -> sbufP[cur] ----
        float4 r_a, r_b;
        {
            const float* row0 = &xbuf[cur][0][lane * XSTRIDE + scolbase + 2];
            float2 a0 = *reinterpret_cast<const float2*>(row0);       // x[w-2,w-1]
            float2 a1 = *reinterpret_cast<const float2*>(row0 + 2);   // x[w  ,w+1]
            float2 a2 = *reinterpret_cast<const float2*>(row0 + 4);   // x[w+2,w+3]
            float2 a3 = *reinterpret_cast<const float2*>(row0 + 6);   // x[w+4,w+5]
            r_a.x = wW0*a0.x + wW1*a0.y + wW2*a1.x + wW3*a1.y + wW4*a2.x;
            r_a.y = wW0*a0.y + wW1*a1.x + wW2*a1.y + wW3*a2.x + wW4*a2.y;
            r_a.z = wW0*a1.x + wW1*a1.y + wW2*a2.x + wW3*a2.y + wW4*a3.x;
            r_a.w = wW0*a1.y + wW1*a2.x + wW2*a2.y + wW3*a3.x + wW4*a3.y;

            const float* row1 = &xbuf[cur][1][lane * XSTRIDE + scolbase + 2];
            float2 b0 = *reinterpret_cast<const float2*>(row1);
            float2 b1 = *reinterpret_cast<const float2*>(row1 + 2);
            float2 b2 = *reinterpret_cast<const float2*>(row1 + 4);
            float2 b3 = *reinterpret_cast<const float2*>(row1 + 6);
            r_b.x = wW0*b0.x + wW1*b0.y + wW2*b1.x + wW3*b1.y + wW4*b2.x;
            r_b.y = wW0*b0.y + wW1*b1.x + wW2*b1.y + wW3*b2.x + wW4*b2.y;
            r_b.z = wW0*b1.x + wW1*b1.y + wW2*b2.x + wW3*b2.y + wW4*b3.x;
            r_b.w = wW0*b1.y + wW1*b2.x + wW2*b2.y + wW3*b3.x + wW4*b3.y;
        }

        if (ii >= 2) {
            float* sa = cur ? sbP10 : sbP00;   // row a
            float* sb = cur ? sbP11 : sbP01;   // row b
            float sax = wH0*g1.x + wH1*g2.x + wH2*g3.x + wH3*g4.x + wH4*r_a.x;
            float say = wH0*g1.y + wH1*g2.y + wH2*g3.y + wH3*g4.y + wH4*r_a.y;
            float saz = wH0*g1.z + wH1*g2.z + wH2*g3.z + wH3*g4.z + wH4*r_a.z;
            float saw = wH0*g1.w + wH1*g2.w + wH2*g3.w + wH3*g4.w + wH4*r_a.w;
            *reinterpret_cast<float2*>(sa)        = make_float2(sax, say);
            *reinterpret_cast<float2*>(sa + PSTR) = make_float2(saz, saw);
            float sbx = wH0*g2.x + wH1*g3.x + wH2*g4.x + wH3*r_a.x + wH4*r_b.x;
            float sby = wH0*g2.y + wH1*g3.y + wH2*g4.y + wH3*r_a.y + wH4*r_b.y;
            float sbz = wH0*g2.z + wH1*g3.z + wH2*g4.z + wH3*r_a.z + wH4*r_b.z;
            float sbw = wH0*g2.w + wH1*g3.w + wH2*g4.w + wH3*r_a.w + wH4*r_b.w;
            *reinterpret_cast<float2*>(sb)        = make_float2(sbx, sby);
            *reinterpret_cast<float2*>(sb + PSTR) = make_float2(sbz, sbw);
        }
        // ring shift by 2 (rename)
        g1 = g3; g2 = g4; g3 = r_a; g4 = r_b;

        // ---- 3. phase C (threads 0-127): T-conv 8t x 2w, rolling 3-quad consume ----
        if (doC && ii >= 3) {
            const float* sp = sbufP[cur ^ 1][rr];
            float4 Qa = *reinterpret_cast<const float4*>(sp + qoff0);
            float4 Qb = *reinterpret_cast<const float4*>(sp + qoff1);
            float4 Qc = *reinterpret_cast<const float4*>(sp + qoff2);
            Qa.x *= mlo; Qa.y *= mlo; Qa.z *= mlo; Qa.w *= mlo;
            // k=0,1 (t0, t0+1)
            *reinterpret_cast<float2*>(op) = make_float2(
                wT0*Qa.x + wT1*Qa.z + wT2*Qb.x + wT3*Qb.z + wT4*Qc.x,
                wT0*Qa.y + wT1*Qa.w + wT2*Qb.y + wT3*Qb.w + wT4*Qc.y);
            *reinterpret_cast<float2*>(op + 1 * HW) = make_float2(
                wT0*Qa.z + wT1*Qb.x + wT2*Qb.z + wT3*Qc.x + wT4*Qc.z,
                wT0*Qa.w + wT1*Qb.y + wT2*Qb.w + wT3*Qc.y + wT4*Qc.w);
            Qa = *reinterpret_cast<const float4*>(sp + qoff3);   // reuse reg slot
            // k=2,3 (t0+2, t0+3): window Qb,Qc,Qa
            *reinterpret_cast<float2*>(op + 2 * HW) = make_float2(
                wT0*Qb.x + wT1*Qb.z + wT2*Qc.x + wT3*Qc.z + wT4*Qa.x,
                wT0*Qb.y + wT1*Qb.w + wT2*Qc.y + wT3*Qc.w + wT4*Qa.y);
            *reinterpret_cast<float2*>(op + 3 * HW) = make_float2(
                wT0*Qb.z + wT1*Qc.x + wT2*Qc.z + wT3*Qa.x + wT4*Qa.z,
                wT0*Qb.w + wT1*Qc.y + wT2*Qc.w + wT3*Qa.y + wT4*Qa.w);
            Qb = *reinterpret_cast<const float4*>(sp + qoff4);
            // k=4,5 (t0+4, t0+5): window Qc,Qa,Qb
            *reinterpret_cast<float2*>(op + 4 * HW) = make_float2(
                wT0*Qc.x + wT1*Qc.z + wT2*Qa.x + wT3*Qa.z + wT4*Qb.x,
                wT0*Qc.y + wT1*Qc.w + wT2*Qa.y + wT3*Qa.w + wT4*Qb.y);
            *reinterpret_cast<float2*>(op + 5 * HW) = make_float2(
                wT0*Qc.z + wT1*Qa.x + wT2*Qa.z + wT3*Qb.x + wT4*Qb.z,
                wT0*Qc.w + wT1*Qa.y + wT2*Qa.w + wT3*Qb.y + wT4*Qb.w);
            Qc = *reinterpret_cast<const float4*>(sp + qoff5);
            Qc.x *= mhi; Qc.y *= mhi; Qc.z *= mhi; Qc.w *= mhi;
            // k=6,7 (t0+6, t0+7): window Qa,Qb,Qc
            *reinterpret_cast<float2*>(op + 6 * HW) = make_float2(
                wT0*Qa.x + wT1*Qa.z + wT2*Qb.x + wT3*Qb.z + wT4*Qc.x,
                wT0*Qa.y + wT1*Qa.w + wT2*Qb.y + wT3*Qb.w + wT4*Qc.y);
            *reinterpret_cast<float2*>(op + 7 * HW) = make_float2(
                wT0*Qa.z + wT1*Qb.x + wT2*Qb.z + wT3*Qc.x + wT4*Qc.z,
                wT0*Qa.w + wT1*Qb.y + wT2*Qb.w + wT3*Qc.y + wT4*Qc.w);
        }
        op += 2 * WW;

        // ---- 4. commit prefetched rows into xbuf[cur^1] ----
        *reinterpret_cast<float4*>(cur ? xsA00 : xsA10) = pa0;
        *reinterpret_cast<float4*>(cur ? xsA01 : xsA11) = pa1;
        if (hasB) {
            *reinterpret_cast<float4*>(cur ? xsB00 : xsB10) = pb0;
            *reinterpret_cast<float4*>(cur ? xsB01 : xsB11) = pb1;
        }

        __syncthreads();
        // barrier orders: xbuf[cur^1] STS vs next-iter LDS; sbufP[cur] writes vs
        // next-iter phase-C reads; phase-C reads of sbufP[cur^1] vs iter+1 writes.
    }

    // ---- epilogue: last 2 output rows from sbufP[(NIT-1)&1] ----
    if (doC) {
        const float* sp = sbufP[(NIT - 1) & 1][rr];
        float4 Qa = *reinterpret_cast<const float4*>(sp + qoff0);
        float4 Qb = *reinterpret_cast<const float4*>(sp + qoff1);
        float4 Qc = *reinterpret_cast<const float4*>(sp + qoff2);
        Qa.x *= mlo; Qa.y *= mlo; Qa.z *= mlo; Qa.w *= mlo;
        // op has advanced 2*NIT rows: points at row h0 + 30 + rr
        *reinterpret_cast<float2*>(op) = make_float2(
            wT0*Qa.x + wT1*Qa.z + wT2*Qb.x + wT3*Qb.z + wT4*Qc.x,
            wT0*Qa.y + wT1*Qa.w + wT2*Qb.y + wT3*Qb.w + wT4*Qc.y);
        *reinterpret_cast<float2*>(op + 1 * HW) = make_float2(
            wT0*Qa.z + wT1*Qb.x + wT2*Qb.z + wT3*Qc.x + wT4*Qc.z,
            wT0*Qa.w + wT1*Qb.y + wT2*Qb.w + wT3*Qc.y + wT4*Qc.w);
        Qa = *reinterpret_cast<const float4*>(sp + qoff3);
        *reinterpret_cast<float2*>(op + 2 * HW) = make_float2(
            wT0*Qb.x + wT1*Qb.z + wT2*Qc.x + wT3*Qc.z + wT4*Qa.x,
            wT0*Qb.y + wT1*Qb.w + wT2*Qc.y + wT3*Qc.w + wT4*Qa.y);
        *reinterpret_cast<float2*>(op + 3 * HW) = make_float2(
            wT0*Qb.z + wT1*Qc.x + wT2*Qc.z + wT3*Qa.x + wT4*Qa.z,
            wT0*Qb.w + wT1*Qc.y + wT2*Qc.w + wT3*Qa.y + wT4*Qa.w);
        Qb = *reinterpret_cast<const float4*>(sp + qoff4);
        *reinterpret_cast<float2*>(op + 4 * HW) = make_float2(
            wT0*Qc.x + wT1*Qc.z + wT2*Qa.x + wT3*Qa.z + wT4*Qb.x,
            wT0*Qc.y + wT1*Qc.w + wT2*Qa.y + wT3*Qa.w + wT4*Qb.y);
        *reinterpret_cast<float2*>(op + 5 * HW) = make_float2(
            wT0*Qc.z + wT1*Qa.x + wT2*Qa.z + wT3*Qb.x + wT4*Qb.z,
            wT0*Qc.w + wT1*Qa.y + wT2*Qa.w + wT3*Qb.y + wT4*Qb.w);
        Qc = *reinterpret_cast<const float4*>(sp + qoff5);
        Qc.x *= mhi; Qc.y *= mhi; Qc.z *= mhi; Qc.w *= mhi;
        *reinterpret_cast<float2*>(op + 6 * HW) = make_float2(
            wT0*Qa.x + wT1*Qa.z + wT2*Qb.x + wT3*Qb.z + wT4*Qc.x,
            wT0*Qa.y + wT1*Qa.w + wT2*Qb.y + wT3*Qb.w + wT4*Qc.y);
        *reinterpret_cast<float2*>(op + 7 * HW) = make_float2(
            wT0*Qa.z + wT1*Qb.x + wT2*Qb.z + wT3*Qc.x + wT4*Qc.z,
            wT0*Qa.w + wT1*Qb.y + wT2*Qb.w + wT3*Qc.y + wT4*Qc.w);
    }
}

extern "C" void kernel_launch(void* const* d_in, const int* in_sizes, int n_in,
                              void* d_out, int out_size)
{
    const float* x  = (const float*)d_in[0];
    const float* w1 = (const float*)d_in[1];
    const float* w2 = (const float*)d_in[2];
    const float* w3 = (const float*)d_in[3];
    float* out = (float*)d_out;

    // 24 (n*c) * 8 (w tiles) * 8 (h chunks) = 1536 blocks
    sepconv3d_fused<<<NN * CC * (WW / WT) * (HH / HC), 256>>>(x, w1, w2, w3, out);
}